// round 12
// baseline (speedup 1.0000x reference)
#include <cuda_runtime.h>
#include <cuda_bf16.h>
#include <mma.h>
#include <cstdint>

using namespace nvcuda;

// ---------------- problem constants ----------------
#define NN 40000      // nodes
#define EE 640000     // edges
#define CD 128        // channels (= IN = H*D)
#define HH 8          // heads
#define DD 16         // dim per head
#define EDD 64        // edge feature dim
#define C2 256        // FFN hidden
#define EPS 1e-5f
#define NB 157        // ceil(NN/256)

// ---------------- scratch (static device globals; no allocs allowed) ----------------
__device__ float    g_qd[(size_t)NN * CD];
__device__ float    g_kd[(size_t)NN * CD];
__device__ float    g_vd[(size_t)NN * CD];
__device__ float    g_eb[(size_t)EE * HH];    // per-edge bias (edge order)
__device__ float    g_ebp[(size_t)EE * HH];   // per-edge bias (CSR order)
__device__ float    g_agg[(size_t)NN * CD];
__device__ float    g_rst[(size_t)NN * CD];
__device__ float    g_h1[(size_t)NN * C2];
__device__ float    g_h2[(size_t)NN * CD];
__device__ float    g_stats[4 * CD];
__device__ float    g_coef[4 * CD];
// CSR
__device__ int      g_cnt[NN];
__device__ int      g_pos[NN];
__device__ int      g_row[NN + 1];
__device__ int      g_bsum[NB];
__device__ int      g_esrc[EE];
// preconverted weights (bf16 hi/lo)
#define WOFF_Q  0
#define WOFF_K  16384
#define WOFF_V  32768
#define WOFF_O  49152
#define WOFF_1  65536
#define WOFF_2  98304
#define WTOT    131072
__device__ __align__(16) __nv_bfloat16 g_wh[WTOT];
__device__ __align__(16) __nv_bfloat16 g_wl[WTOT];

// ---------------- cp.async helpers ----------------
__device__ __forceinline__ void cp_async16(uint32_t saddr, const void* gaddr) {
    asm volatile("cp.async.ca.shared.global [%0], [%1], 16;" :: "r"(saddr), "l"(gaddr));
}
#define CP_COMMIT() asm volatile("cp.async.commit_group;" ::: "memory")
#define CP_WAIT0()  asm volatile("cp.async.wait_group 0;" ::: "memory")

// ---------------- side-stream init: zero CSR counters ----------------
__global__ void zerocnt_kernel() {
    int i = blockIdx.x * 256 + threadIdx.x;
    if (i < NN) { g_cnt[i] = 0; g_pos[i] = 0; }
}

// ---------------- main-stream init: weights + stats ----------------
__global__ void initconv_kernel(const float* __restrict__ Wq, const float* __restrict__ Wk,
                                const float* __restrict__ Wv, const float* __restrict__ Wo,
                                const float* __restrict__ W1, const float* __restrict__ W2) {
    int i = blockIdx.x * 256 + threadIdx.x;
    if (i < 4 * CD) g_stats[i] = 0.f;
    if (i < WTOT) {
        const float* src; int off;
        if (i < WOFF_K)      { src = Wq; off = i - WOFF_Q; }
        else if (i < WOFF_V) { src = Wk; off = i - WOFF_K; }
        else if (i < WOFF_O) { src = Wv; off = i - WOFF_V; }
        else if (i < WOFF_1) { src = Wo; off = i - WOFF_O; }
        else if (i < WOFF_2) { src = W1; off = i - WOFF_1; }
        else                 { src = W2; off = i - WOFF_2; }
        float v = src[off];
        __nv_bfloat16 h = __float2bfloat16(v);
        g_wh[i] = h;
        g_wl[i] = __float2bfloat16(v - __bfloat162float(h));
    }
}

// ---------------- multi-block exclusive scan (3 phases) ----------------
__device__ __forceinline__ int block_scan256(int x, int* total) {
    __shared__ int ws[8];
    const int t = threadIdx.x, lane = t & 31, wid = t >> 5;
    int v = x;
#pragma unroll
    for (int o = 1; o < 32; o <<= 1) {
        int u = __shfl_up_sync(0xffffffffu, v, o);
        if (lane >= o) v += u;
    }
    if (lane == 31) ws[wid] = v;
    __syncthreads();
    if (wid == 0 && lane < 8) {
        int w = ws[lane];
#pragma unroll
        for (int o = 1; o < 8; o <<= 1) {
            int u = __shfl_up_sync(0x000000ffu, w, o);
            if (lane >= o) w += u;
        }
        ws[lane] = w;
    }
    __syncthreads();
    const int off = (wid > 0) ? ws[wid - 1] : 0;
    *total = ws[7];
    return off + v;
}

__global__ void __launch_bounds__(256)
scan1_kernel() {
    const int idx = blockIdx.x * 256 + threadIdx.x;
    int x = (idx < NN) ? g_cnt[idx] : 0;
    int total;
    int inc = block_scan256(x, &total);
    if (idx < NN) g_row[idx] = inc - x;
    if (threadIdx.x == 255) g_bsum[blockIdx.x] = total;
}

__global__ void __launch_bounds__(256)
scan2_kernel() {
    const int t = threadIdx.x;
    int x = (t < NB) ? g_bsum[t] : 0;
    int total;
    int inc = block_scan256(x, &total);
    if (t < NB) g_bsum[t] = inc - x;
}

__global__ void __launch_bounds__(256)
scan3_kernel() {
    const int idx = blockIdx.x * 256 + threadIdx.x;
    if (idx < NN) g_row[idx] += g_bsum[blockIdx.x];
    if (idx == 0) g_row[NN] = EE;
}

// ---------------- scatter: CSR adjacency + permute eb into CSR order ----------------
__global__ void scatter_kernel(const int* __restrict__ src, const int* __restrict__ dst) {
    int e = blockIdx.x * 256 + threadIdx.x;
    const int d = dst[e];
    int p = atomicAdd(&g_pos[d], 1);
    int o = g_row[d] + p;
    g_esrc[o] = src[e];
    float4 a = ((const float4*)g_eb)[(size_t)e * 2 + 0];
    float4 b = ((const float4*)g_eb)[(size_t)e * 2 + 1];
    ((float4*)g_ebp)[(size_t)o * 2 + 0] = a;
    ((float4*)g_ebp)[(size_t)o * 2 + 1] = b;
}

// ---------------- fused one-pass attention (warp per node, depth-2 pipeline) ----------------
__global__ void __launch_bounds__(256)
attn_kernel() {
    const int warpId = (blockIdx.x * 256 + threadIdx.x) >> 5;
    const int lane = threadIdx.x & 31;
    if (warpId >= NN) return;
    const int n = warpId;
    const int r0 = g_row[n], r1 = g_row[n + 1];
    const int h = lane >> 2;

    float4 qv = ((const float4*)g_qd)[(size_t)n * 32 + lane];

    float m = -3.0e38f, den = 0.f;
    float4 acc = make_float4(0.f, 0.f, 0.f, 0.f);

    float4 kvb0, vvb0, kvb1, vvb1;
    float eb0 = 0.f, eb1 = 0.f;
    if (r0 < r1) {
        const int s = g_esrc[r0];
        kvb0 = ((const float4*)g_kd)[(size_t)s * 32 + lane];
        vvb0 = ((const float4*)g_vd)[(size_t)s * 32 + lane];
        eb0 = __ldg(&g_ebp[(size_t)r0 * HH + h]);
    }
    if (r0 + 1 < r1) {
        const int s = g_esrc[r0 + 1];
        kvb1 = ((const float4*)g_kd)[(size_t)s * 32 + lane];
        vvb1 = ((const float4*)g_vd)[(size_t)s * 32 + lane];
        eb1 = __ldg(&g_ebp[(size_t)(r0 + 1) * HH + h]);
    }

#define ATTN_BODY(KV, VV, EBV)                                              \
    {                                                                       \
        float p = qv.x * (KV).x + qv.y * (KV).y + qv.z * (KV).z + qv.w * (KV).w; \
        p += __shfl_xor_sync(0xffffffffu, p, 1);                            \
        p += __shfl_xor_sync(0xffffffffu, p, 2);                            \
        const float sc = p * 0.25f + (EBV);                                 \
        const float nm = fmaxf(m, sc);                                      \
        const float corr = __expf(m - nm);                                  \
        const float w = __expf(sc - nm);                                    \
        m = nm;                                                             \
        den = den * corr + w;                                               \
        acc.x = acc.x * corr + w * (VV).x;                                  \
        acc.y = acc.y * corr + w * (VV).y;                                  \
        acc.z = acc.z * corr + w * (VV).z;                                  \
        acc.w = acc.w * corr + w * (VV).w;                                  \
    }

    int i = r0;
    while (i < r1) {
        {
            float4 kv = kvb0, vv = vvb0; float ebv = eb0;
            if (i + 2 < r1) {
                const int ns = g_esrc[i + 2];
                kvb0 = ((const float4*)g_kd)[(size_t)ns * 32 + lane];
                vvb0 = ((const float4*)g_vd)[(size_t)ns * 32 + lane];
                eb0 = __ldg(&g_ebp[(size_t)(i + 2) * HH + h]);
            }
            ATTN_BODY(kv, vv, ebv);
        }
        i++;
        if (i >= r1) break;
        {
            float4 kv = kvb1, vv = vvb1; float ebv = eb1;
            if (i + 2 < r1) {
                const int ns = g_esrc[i + 2];
                kvb1 = ((const float4*)g_kd)[(size_t)ns * 32 + lane];
                vvb1 = ((const float4*)g_vd)[(size_t)ns * 32 + lane];
                eb1 = __ldg(&g_ebp[(size_t)(i + 2) * HH + h]);
            }
            ATTN_BODY(kv, vv, ebv);
        }
        i++;
    }
#undef ATTN_BODY

    const float inv = (den > 0.f) ? (1.f / den) : 0.f;
    acc.x *= inv; acc.y *= inv; acc.z *= inv; acc.w *= inv;
    ((float4*)g_agg)[(size_t)n * 32 + lane] = acc;
}

// ---------------- WMMA bf16-split GEMM core — double-buffered pipeline ----------------
#define LDS_AB 72
#define LDS_C 132

template <int BM>
struct TCL {
    static constexpr int AP = BM * LDS_AB * 2;    // one A plane (hi or lo)
    static constexpr int BP = 128 * LDS_AB * 2;   // one B plane
    // layout: [AH0 AL0 | AH1 AL1 | BH0 BL0 | BH1 BL1]
    static constexpr int A_TOT = 4 * AP;
    static constexpr int SMEM = 4 * AP + 4 * BP;
};
#define SMEM_TC128 (TCL<128>::SMEM)   // 147456
#define SMEM_TC64  (TCL<64>::SMEM)    // 110592

template <int BM, bool RELU, bool BIAS, bool RES, bool BNIN, bool RESBN, bool STATS>
__device__ __forceinline__ void gemm_core(
    const float* __restrict__ X,
    const __nv_bfloat16* __restrict__ WH, const __nv_bfloat16* __restrict__ WL,
    const float* __restrict__ bias, const float* __restrict__ res,
    const float* __restrict__ coefA, const float* __restrict__ coefR,
    float* __restrict__ stats, float* __restrict__ Y,
    int M, int K, int Co, int bm, int bn, char* smem) {
    constexpr int RF = BM / 64;
    constexpr int AP = TCL<BM>::AP;
    constexpr int BP = TCL<BM>::BP;
    constexpr int A_TOT = TCL<BM>::A_TOT;
    constexpr int NIT = BM / 16;       // A convert iterations
    const int tid = threadIdx.x;
    const int warp = tid >> 5;
    const int wm = (warp & 3) * (BM / 4);
    const int wn = (warp >> 2) * 64;
    const uint32_t sb = (uint32_t)__cvta_generic_to_shared(smem);

    wmma::fragment<wmma::accumulator, 16, 16, 16, float> acc[RF][4];
#pragma unroll
    for (int i = 0; i < RF; i++)
#pragma unroll
        for (int j = 0; j < 4; j++)
            wmma::fill_fragment(acc[i][j], 0.f);

    const int nch = K >> 6;
    float4 aregs[NIT];

    // ---- prologue: LDG A(0), cp.async B(0), convert A(0) into buffer 0 ----
#pragma unroll
    for (int it = 0; it < NIT; it++) {
        const int idx = tid + it * 256;
        const int row = idx >> 4;
        const int c4 = (idx & 15) << 2;
        const int r = min(bm + row, M - 1);
        aregs[it] = *(const float4*)(X + (size_t)r * K + c4);
    }
#pragma unroll
    for (int it = 0; it < 4; it++) {
        const int idx = tid + it * 256;
        const int row = idx >> 3;
        const int c8 = (idx & 7) << 3;
        const size_t g = (size_t)(bn + row) * K + c8;
        const uint32_t so = sb + (uint32_t)A_TOT + (uint32_t)(row * LDS_AB + c8) * 2;
        cp_async16(so, WH + g);
        cp_async16(so + BP, WL + g);
    }
    CP_COMMIT();
#pragma unroll
    for (int it = 0; it < NIT; it++) {
        const int idx = tid + it * 256;
        const int row = idx >> 4;
        const int c4 = (idx & 15) << 2;
        float4 v = aregs[it];
        if (BNIN) {
            float4 s4 = *(const float4*)(coefA + c4);
            float4 t4 = *(const float4*)(coefA + 128 + c4);
            v.x = v.x * s4.x + t4.x; v.y = v.y * s4.y + t4.y;
            v.z = v.z * s4.z + t4.z; v.w = v.w * s4.w + t4.w;
        }
        __nv_bfloat162 h0 = __floats2bfloat162_rn(v.x, v.y);
        __nv_bfloat162 h1 = __floats2bfloat162_rn(v.z, v.w);
        float2 f0 = __bfloat1622float2(h0);
        float2 f1 = __bfloat1622float2(h1);
        __nv_bfloat162 l0 = __floats2bfloat162_rn(v.x - f0.x, v.y - f0.y);
        __nv_bfloat162 l1 = __floats2bfloat162_rn(v.z - f1.x, v.w - f1.y);
        uint2 ph, pl;
        ph.x = *(uint32_t*)&h0; ph.y = *(uint32_t*)&h1;
        pl.x = *(uint32_t*)&l0; pl.y = *(uint32_t*)&l1;
        *(uint2*)(smem + ((size_t)row * LDS_AB + c4) * 2) = ph;
        *(uint2*)(smem + AP + ((size_t)row * LDS_AB + c4) * 2) = pl;
    }
    CP_WAIT0();
    __syncthreads();

    // ---- mainloop: MMA(ch) overlaps LDG A(ch+1) + cp.async B(ch+1) ----
    for (int ch = 0; ch < nch; ch++) {
        const int p = ch & 1;
        const bool more = (ch + 1) < nch;
        const int kc1 = (ch + 1) << 6;
        if (more) {
            // B(ch+1) -> buffer p^1 (async, overlaps MMA)
#pragma unroll
            for (int it = 0; it < 4; it++) {
                const int idx = tid + it * 256;
                const int row = idx >> 3;
                const int c8 = (idx & 7) << 3;
                const size_t g = (size_t)(bn + row) * K + kc1 + c8;
                const uint32_t so = sb + (uint32_t)(A_TOT + (p ^ 1) * 2 * BP)
                                  + (uint32_t)(row * LDS_AB + c8) * 2;
                cp_async16(so, WH + g);
                cp_async16(so + BP, WL + g);
            }
            CP_COMMIT();
            // A(ch+1) -> registers (consumed after MMA; latency hidden)
#pragma unroll
            for (int it = 0; it < NIT; it++) {
                const int idx = tid + it * 256;
                const int row = idx >> 4;
                const int c4 = (idx & 15) << 2;
                const int r = min(bm + row, M - 1);
                aregs[it] = *(const float4*)(X + (size_t)r * K + kc1 + c4);
            }
        }

        const __nv_bfloat16* sAh = (const __nv_bfloat16*)(smem + p * 2 * AP);
        const __nv_bfloat16* sAl = (const __nv_bfloat16*)(smem + p * 2 * AP + AP);
        const __nv_bfloat16* sBh = (const __nv_bfloat16*)(smem + A_TOT + p * 2 * BP);
        const __nv_bfloat16* sBl = (const __nv_bfloat16*)(smem + A_TOT + p * 2 * BP + BP);
#pragma unroll
        for (int ks = 0; ks < 4; ks++) {
            const int k0 = ks * 16;
            wmma::fragment<wmma::matrix_a, 16, 16, 16, __nv_bfloat16, wmma::row_major> ah[RF], al[RF];
#pragma unroll
            for (int i = 0; i < RF; i++) {
                wmma::load_matrix_sync(ah[i], sAh + (size_t)(wm + 16 * i) * LDS_AB + k0, LDS_AB);
                wmma::load_matrix_sync(al[i], sAl + (size_t)(wm + 16 * i) * LDS_AB + k0, LDS_AB);
            }
#pragma unroll
            for (int j = 0; j < 4; j++) {
                wmma::fragment<wmma::matrix_b, 16, 16, 16, __nv_bfloat16, wmma::col_major> bh, bl;
                wmma::load_matrix_sync(bh, sBh + (size_t)(wn + 16 * j) * LDS_AB + k0, LDS_AB);
                wmma::load_matrix_sync(bl, sBl + (size_t)(wn + 16 * j) * LDS_AB + k0, LDS_AB);
#pragma unroll
                for (int i = 0; i < RF; i++) {
                    wmma::mma_sync(acc[i][j], ah[i], bh, acc[i][j]);
                    wmma::mma_sync(acc[i][j], ah[i], bl, acc[i][j]);
                    wmma::mma_sync(acc[i][j], al[i], bh, acc[i][j]);
                }
            }
        }

        if (more) {
            // convert + store A(ch+1) into buffer p^1
#pragma unroll
            for (int it = 0; it < NIT; it++) {
                const int idx = tid + it * 256;
                const int row = idx >> 4;
                const int c4 = (idx & 15) << 2;
                float4 v = aregs[it];
                if (BNIN) {
                    const int c = kc1 + c4;
                    float4 s4 = *(const float4*)(coefA + c);
                    float4 t4 = *(const float4*)(coefA + 128 + c);
                    v.x = v.x * s4.x + t4.x; v.y = v.y * s4.y + t4.y;
                    v.z = v.z * s4.z + t4.z; v.w = v.w * s4.w + t4.w;
                }
                __nv_bfloat162 h0 = __floats2bfloat162_rn(v.x, v.y);
                __nv_bfloat162 h1 = __floats2bfloat162_rn(v.z, v.w);
                float2 f0 = __bfloat1622float2(h0);
                float2 f1 = __bfloat1622float2(h1);
                __nv_bfloat162 l0 = __floats2bfloat162_rn(v.x - f0.x, v.y - f0.y);
                __nv_bfloat162 l1 = __floats2bfloat162_rn(v.z - f1.x, v.w - f1.y);
                uint2 ph, pl;
                ph.x = *(uint32_t*)&h0; ph.y = *(uint32_t*)&h1;
                pl.x = *(uint32_t*)&l0; pl.y = *(uint32_t*)&l1;
                *(uint2*)(smem + (p ^ 1) * 2 * AP + ((size_t)row * LDS_AB + c4) * 2) = ph;
                *(uint2*)(smem + (p ^ 1) * 2 * AP + AP + ((size_t)row * LDS_AB + c4) * 2) = pl;
            }
            CP_WAIT0();
        }
        __syncthreads();
    }

    // ---- epilogue ----
    float* sC = (float*)smem;
#pragma unroll
    for (int i = 0; i < RF; i++)
#pragma unroll
        for (int j = 0; j < 4; j++)
            wmma::store_matrix_sync(sC + (size_t)(wm + 16 * i) * LDS_C + wn + 16 * j,
                                    acc[i][j], LDS_C, wmma::mem_row_major);
    __syncthreads();

    float st_s[4] = {0.f, 0.f, 0.f, 0.f};
    float st_q[4] = {0.f, 0.f, 0.f, 0.f};
#pragma unroll
    for (int it = 0; it < BM / 8; it++) {
        const int idx = tid + it * 256;
        const int row = idx >> 5;
        const int c = (idx & 31) << 2;
        const int m = bm + row;
        if (m < M) {
            const int n = bn + c;
            float4 o = *(const float4*)(sC + (size_t)row * LDS_C + c);
            if (BIAS) {
                float4 b4 = *(const float4*)&bias[n];
                o.x += b4.x; o.y += b4.y; o.z += b4.z; o.w += b4.w;
            }
            if (RELU) {
                o.x = fmaxf(o.x, 0.f); o.y = fmaxf(o.y, 0.f);
                o.z = fmaxf(o.z, 0.f); o.w = fmaxf(o.w, 0.f);
            }
            if (RES) {
                float4 r4 = *(const float4*)&res[(size_t)m * Co + n];
                if (RESBN) {
                    float4 s4 = *(const float4*)(coefR + c);
                    float4 t4 = *(const float4*)(coefR + 128 + c);
                    r4.x = r4.x * s4.x + t4.x; r4.y = r4.y * s4.y + t4.y;
                    r4.z = r4.z * s4.z + t4.z; r4.w = r4.w * s4.w + t4.w;
                }
                o.x += r4.x; o.y += r4.y; o.z += r4.z; o.w += r4.w;
            }
            *(float4*)&Y[(size_t)m * Co + n] = o;
            if (STATS) {
                st_s[0] += o.x; st_s[1] += o.y; st_s[2] += o.z; st_s[3] += o.w;
                st_q[0] += o.x * o.x; st_q[1] += o.y * o.y;
                st_q[2] += o.z * o.z; st_q[3] += o.w * o.w;
            }
        }
    }
    if (STATS) {
        __syncthreads();
        float* sP = (float*)smem;
#pragma unroll
        for (int j = 0; j < 4; j++) { sP[tid * 8 + j] = st_s[j]; sP[tid * 8 + 4 + j] = st_q[j]; }
        __syncthreads();
        if (tid < 128) {
            const int cg = tid >> 2, sub = tid & 3;
            float s = 0.f, qq = 0.f;
#pragma unroll
            for (int rg = 0; rg < 8; rg++) {
                const int tt = rg * 32 + cg;
                s += sP[tt * 8 + sub];
                qq += sP[tt * 8 + 4 + sub];
            }
            atomicAdd(&stats[bn + tid], s);
            atomicAdd(&stats[128 + bn + tid], qq);
        }
    }
}

template <bool RELU, bool BIAS, bool RES, bool BNIN, bool RESBN, bool STATS>
__global__ void __launch_bounds__(256, 1)
tc_gemm_kernel(const float* __restrict__ X,
               const __nv_bfloat16* __restrict__ WH, const __nv_bfloat16* __restrict__ WL,
               const float* __restrict__ bias, const float* __restrict__ res,
               const float* __restrict__ coefA, const float* __restrict__ coefR,
               float* __restrict__ stats, float* __restrict__ Y, int M, int K, int Co) {
    extern __shared__ char smem[];
    gemm_core<128, RELU, BIAS, RES, BNIN, RESBN, STATS>(
        X, WH, WL, bias, res, coefA, coefR, stats, Y, M, K, Co,
        blockIdx.x * 128, blockIdx.y * 128, smem);
}

template <bool RELU, bool BIAS, bool RES, bool BNIN, bool RESBN, bool STATS>
__global__ void __launch_bounds__(256, 2)
tc_gemm64_kernel(const float* __restrict__ X,
                 const __nv_bfloat16* __restrict__ WH, const __nv_bfloat16* __restrict__ WL,
                 const float* __restrict__ bias, const float* __restrict__ res,
                 const float* __restrict__ coefA, const float* __restrict__ coefR,
                 float* __restrict__ stats, float* __restrict__ Y, int M, int K, int Co) {
    extern __shared__ char smem[];
    gemm_core<64, RELU, BIAS, RES, BNIN, RESBN, STATS>(
        X, WH, WL, bias, res, coefA, coefR, stats, Y, M, K, Co,
        blockIdx.x * 64, blockIdx.y * 128, smem);
}

__global__ void __launch_bounds__(256, 1)
qkv_gemm_kernel(const float* __restrict__ q, const float* __restrict__ k,
                const float* __restrict__ v) {
    extern __shared__ char smem[];
    const int z = blockIdx.z;
    const float* X = (z == 0) ? q : (z == 1) ? k : v;
    float* Y = (z == 0) ? g_qd : (z == 1) ? g_kd : g_vd;
    gemm_core<128, false, false, false, false, false, false>(
        X, g_wh + z * 16384, g_wl + z * 16384,
        nullptr, nullptr, nullptr, nullptr, nullptr, Y, NN, CD, CD,
        blockIdx.x * 128, 0, smem);
}

// ---------------- edge bias + dst histogram (fused) ----------------
__global__ void __launch_bounds__(256)
eb_kernel(const float* __restrict__ ef, const float* __restrict__ We,
          const float* __restrict__ be, const int* __restrict__ dst) {
    __shared__ float sWe[HH * EDD];
    __shared__ float sbe[HH];
    for (int i = threadIdx.x; i < HH * EDD; i += 256) sWe[i] = We[i];
    if (threadIdx.x < HH) sbe[threadIdx.x] = be[threadIdx.x];
    __syncthreads();

    const int e = blockIdx.x * 256 + threadIdx.x;
    atomicAdd(&g_cnt[dst[e]], 1);
    const float4* efp = (const float4*)(ef + (size_t)e * EDD);
    float acc[HH];
#pragma unroll
    for (int h = 0; h < HH; h++) acc[h] = sbe[h];
#pragma unroll
    for (int j4 = 0; j4 < EDD / 4; j4++) {
        float4 v = efp[j4];
#pragma unroll
        for (int h = 0; h < HH; h++) {
            float4 w = *(const float4*)&sWe[h * EDD + j4 * 4];
            acc[h] += v.x * w.x + v.y * w.y + v.z * w.z + v.w * w.w;
        }
    }
    float4 o0 = make_float4(acc[0], acc[1], acc[2], acc[3]);
    float4 o1 = make_float4(acc[4], acc[5], acc[6], acc[7]);
    ((float4*)g_eb)[(size_t)e * 2 + 0] = o0;
    ((float4*)g_eb)[(size_t)e * 2 + 1] = o1;
}

// ---------------- BN coefficients ----------------
__global__ void bn_coef_kernel(const float* __restrict__ sums,
                               const float* __restrict__ g, const float* __restrict__ b,
                               float* __restrict__ coef) {
    const int c = threadIdx.x;
    const float inv = 1.f / (float)NN;
    const float mu = sums[c] * inv;
    const float var = sums[128 + c] * inv - mu * mu;
    const float rs = rsqrtf(var + EPS);
    const float sc = rs * g[c];
    coef[c] = sc;
    coef[128 + c] = b[c] - mu * sc;
}

// ---------------- final apply ----------------
__global__ void __launch_bounds__(256)
bn_apply_kernel(const float* __restrict__ X, float* __restrict__ Y,
                const float* __restrict__ coef) {
    const int i = blockIdx.x * 256 + threadIdx.x;
    const int c = i & (CD - 1);
    Y[i] = X[i] * coef[c] + coef[128 + c];
}

// ---------------- launcher ----------------
extern "C" void kernel_launch(void* const* d_in, const int* in_sizes, int n_in,
                              void* d_out, int out_size) {
    const float* q   = (const float*)d_in[0];
    const float* k   = (const float*)d_in[1];
    const float* v   = (const float*)d_in[2];
    const float* ef  = (const float*)d_in[3];
    const int*   src = (const int*)d_in[4];
    const int*   dst = (const int*)d_in[5];
    const float* Wq  = (const float*)d_in[6];
    const float* Wk  = (const float*)d_in[7];
    const float* Wv  = (const float*)d_in[8];
    const float* We  = (const float*)d_in[9];
    const float* be  = (const float*)d_in[10];
    const float* Wo  = (const float*)d_in[11];
    const float* W1  = (const float*)d_in[12];
    const float* b1  = (const float*)d_in[13];
    const float* W2  = (const float*)d_in[14];
    const float* b2  = (const float*)d_in[15];
    const float* g1  = (const float*)d_in[16];
    const float* bt1 = (const float*)d_in[17];
    const float* g2  = (const float*)d_in[18];
    const float* bt2 = (const float*)d_in[19];
    float* out = (float*)d_out;

    float* p_agg; cudaGetSymbolAddress((void**)&p_agg, g_agg);
    float* p_rst; cudaGetSymbolAddress((void**)&p_rst, g_rst);
    float* p_h1; cudaGetSymbolAddress((void**)&p_h1, g_h1);
    float* p_h2; cudaGetSymbolAddress((void**)&p_h2, g_h2);
    float* p_stats; cudaGetSymbolAddress((void**)&p_stats, g_stats);
    float* p_coef; cudaGetSymbolAddress((void**)&p_coef, g_coef);
    __nv_bfloat16* p_wh; cudaGetSymbolAddress((void**)&p_wh, g_wh);
    __nv_bfloat16* p_wl; cudaGetSymbolAddress((void**)&p_wl, g_wl);

    static cudaStream_t s2 = nullptr;
    static cudaEvent_t evF = nullptr, evJ = nullptr;
    if (!s2) {
        cudaStreamCreateWithFlags(&s2, cudaStreamNonBlocking);
        cudaEventCreateWithFlags(&evF, cudaEventDisableTiming);
        cudaEventCreateWithFlags(&evJ, cudaEventDisableTiming);
    }

    cudaFuncSetAttribute(qkv_gemm_kernel, cudaFuncAttributeMaxDynamicSharedMemorySize, SMEM_TC128);
    cudaFuncSetAttribute(tc_gemm64_kernel<false, false, true,  false, false, true >, cudaFuncAttributeMaxDynamicSharedMemorySize, SMEM_TC64);
    cudaFuncSetAttribute(tc_gemm_kernel<true,  true,  false, true,  false, false>, cudaFuncAttributeMaxDynamicSharedMemorySize, SMEM_TC128);
    cudaFuncSetAttribute(tc_gemm64_kernel<false, true,  true,  false, true,  true >, cudaFuncAttributeMaxDynamicSharedMemorySize, SMEM_TC64);

    // fork at t0: edge preprocessing on s2 runs concurrently with initconv+qkv
    cudaEventRecord(evF, 0);
    cudaStreamWaitEvent(s2, evF, 0);

    zerocnt_kernel<<<NB, 256, 0, s2>>>();
    eb_kernel<<<EE / 256, 256, 0, s2>>>(ef, We, be, dst);
    scan1_kernel<<<NB, 256, 0, s2>>>();
    scan2_kernel<<<1, 256, 0, s2>>>();
    scan3_kernel<<<NB, 256, 0, s2>>>();
    scatter_kernel<<<EE / 256, 256, 0, s2>>>(src, dst);
    cudaEventRecord(evJ, s2);

    initconv_kernel<<<WTOT / 256, 256>>>(Wq, Wk, Wv, Wo, W1, W2);

    const dim3 gQKV(313, 1, 3);
    const dim3 g64(625, 1);
    const dim3 gH(313, 2);

    qkv_gemm_kernel<<<gQKV, 256, SMEM_TC128>>>(q, k, v);

    cudaStreamWaitEvent(0, evJ, 0);
    attn_kernel<<<NN / 8, 256>>>();

    // out proj + residual, stats for BN1 fused (BM=64: 625 CTAs, no tail rows)
    tc_gemm64_kernel<false, false, true, false, false, true><<<g64, 256, SMEM_TC64>>>(
        p_agg, p_wh + WOFF_O, p_wl + WOFF_O, nullptr, q, nullptr, nullptr, p_stats, p_rst, NN, CD, CD);
    bn_coef_kernel<<<1, 128>>>(p_stats, g1, bt1, p_coef);

    // FFN
    tc_gemm_kernel<true, true, false, true, false, false><<<gH, 256, SMEM_TC128>>>(
        p_rst, p_wh + WOFF_1, p_wl + WOFF_1, b1, nullptr, p_coef, nullptr, nullptr, p_h1, NN, CD, C2);
    tc_gemm64_kernel<false, true, true, false, true, true><<<g64, 256, SMEM_TC64>>>(
        p_h1, p_wh + WOFF_2, p_wl + WOFF_2, b2, p_rst, nullptr, p_coef, p_stats + 2 * CD, p_h2, NN, C2, CD);
    bn_coef_kernel<<<1, 128>>>(p_stats + 2 * CD, g2, bt2, p_coef + 2 * CD);
    bn_apply_kernel<<<NN * CD / 256, 256>>>(p_h2, out, p_coef + 2 * CD);
}

// round 13
// speedup vs baseline: 1.0576x; 1.0576x over previous
#include <cuda_runtime.h>
#include <cuda_bf16.h>
#include <mma.h>
#include <cstdint>

using namespace nvcuda;

// ---------------- problem constants ----------------
#define NN 40000      // nodes
#define EE 640000     // edges
#define CD 128        // channels (= IN = H*D)
#define HH 8          // heads
#define DD 16         // dim per head
#define EDD 64        // edge feature dim
#define C2 256        // FFN hidden
#define EPS 1e-5f
#define NB 157        // ceil(NN/256)

// ---------------- scratch (static device globals; no allocs allowed) ----------------
__device__ float    g_qd[(size_t)NN * CD];
__device__ float    g_kd[(size_t)NN * CD];
__device__ float    g_vd[(size_t)NN * CD];
__device__ float    g_eb[(size_t)EE * HH];    // per-edge bias (edge order)
__device__ float    g_ebp[(size_t)EE * HH];   // per-edge bias (CSR order)
__device__ float    g_agg[(size_t)NN * CD];
__device__ float    g_rst[(size_t)NN * CD];
__device__ float    g_h1[(size_t)NN * C2];
__device__ float    g_h2[(size_t)NN * CD];
__device__ float    g_stats[4 * CD];
// CSR
__device__ int      g_cnt[NN];
__device__ int      g_pos[NN];
__device__ int      g_row[NN + 1];
__device__ int      g_bsum[NB];
__device__ int      g_esrc[EE];
// preconverted weights (bf16 hi/lo)
#define WOFF_Q  0
#define WOFF_K  16384
#define WOFF_V  32768
#define WOFF_O  49152
#define WOFF_1  65536
#define WOFF_2  98304
#define WTOT    131072
__device__ __align__(16) __nv_bfloat16 g_wh[WTOT];
__device__ __align__(16) __nv_bfloat16 g_wl[WTOT];

// ---------------- cp.async helpers ----------------
__device__ __forceinline__ void cp_async16(uint32_t saddr, const void* gaddr) {
    asm volatile("cp.async.ca.shared.global [%0], [%1], 16;" :: "r"(saddr), "l"(gaddr));
}
#define CP_COMMIT() asm volatile("cp.async.commit_group;" ::: "memory")
#define CP_WAIT0()  asm volatile("cp.async.wait_group 0;" ::: "memory")

// ---------------- side-stream init: zero CSR counters ----------------
__global__ void zerocnt_kernel() {
    int i = blockIdx.x * 256 + threadIdx.x;
    if (i < NN) { g_cnt[i] = 0; g_pos[i] = 0; }
}

// ---------------- main-stream init: weights + stats ----------------
__global__ void initconv_kernel(const float* __restrict__ Wq, const float* __restrict__ Wk,
                                const float* __restrict__ Wv, const float* __restrict__ Wo,
                                const float* __restrict__ W1, const float* __restrict__ W2) {
    int i = blockIdx.x * 256 + threadIdx.x;
    if (i < 4 * CD) g_stats[i] = 0.f;
    if (i < WTOT) {
        const float* src; int off;
        if (i < WOFF_K)      { src = Wq; off = i - WOFF_Q; }
        else if (i < WOFF_V) { src = Wk; off = i - WOFF_K; }
        else if (i < WOFF_O) { src = Wv; off = i - WOFF_V; }
        else if (i < WOFF_1) { src = Wo; off = i - WOFF_O; }
        else if (i < WOFF_2) { src = W1; off = i - WOFF_1; }
        else                 { src = W2; off = i - WOFF_2; }
        float v = src[off];
        __nv_bfloat16 h = __float2bfloat16(v);
        g_wh[i] = h;
        g_wl[i] = __float2bfloat16(v - __bfloat162float(h));
    }
}

// ---------------- multi-block exclusive scan (3 phases) ----------------
__device__ __forceinline__ int block_scan256(int x, int* total) {
    __shared__ int ws[8];
    const int t = threadIdx.x, lane = t & 31, wid = t >> 5;
    int v = x;
#pragma unroll
    for (int o = 1; o < 32; o <<= 1) {
        int u = __shfl_up_sync(0xffffffffu, v, o);
        if (lane >= o) v += u;
    }
    if (lane == 31) ws[wid] = v;
    __syncthreads();
    if (wid == 0 && lane < 8) {
        int w = ws[lane];
#pragma unroll
        for (int o = 1; o < 8; o <<= 1) {
            int u = __shfl_up_sync(0x000000ffu, w, o);
            if (lane >= o) w += u;
        }
        ws[lane] = w;
    }
    __syncthreads();
    const int off = (wid > 0) ? ws[wid - 1] : 0;
    *total = ws[7];
    return off + v;
}

__global__ void __launch_bounds__(256)
scan1_kernel() {
    const int idx = blockIdx.x * 256 + threadIdx.x;
    int x = (idx < NN) ? g_cnt[idx] : 0;
    int total;
    int inc = block_scan256(x, &total);
    if (idx < NN) g_row[idx] = inc - x;
    if (threadIdx.x == 255) g_bsum[blockIdx.x] = total;
}

__global__ void __launch_bounds__(256)
scan2_kernel() {
    const int t = threadIdx.x;
    int x = (t < NB) ? g_bsum[t] : 0;
    int total;
    int inc = block_scan256(x, &total);
    if (t < NB) g_bsum[t] = inc - x;
}

__global__ void __launch_bounds__(256)
scan3_kernel() {
    const int idx = blockIdx.x * 256 + threadIdx.x;
    if (idx < NN) g_row[idx] += g_bsum[blockIdx.x];
    if (idx == 0) g_row[NN] = EE;
}

// ---------------- scatter: CSR adjacency + permute eb into CSR order ----------------
__global__ void scatter_kernel(const int* __restrict__ src, const int* __restrict__ dst) {
    int e = blockIdx.x * 256 + threadIdx.x;
    const int d = dst[e];
    int p = atomicAdd(&g_pos[d], 1);
    int o = g_row[d] + p;
    g_esrc[o] = src[e];
    float4 a = ((const float4*)g_eb)[(size_t)e * 2 + 0];
    float4 b = ((const float4*)g_eb)[(size_t)e * 2 + 1];
    ((float4*)g_ebp)[(size_t)o * 2 + 0] = a;
    ((float4*)g_ebp)[(size_t)o * 2 + 1] = b;
}

// ---------------- fused one-pass attention (warp per node, depth-2 pipeline) ----------------
__global__ void __launch_bounds__(256)
attn_kernel() {
    const int warpId = (blockIdx.x * 256 + threadIdx.x) >> 5;
    const int lane = threadIdx.x & 31;
    if (warpId >= NN) return;
    const int n = warpId;
    const int r0 = g_row[n], r1 = g_row[n + 1];
    const int h = lane >> 2;

    float4 qv = ((const float4*)g_qd)[(size_t)n * 32 + lane];

    float m = -3.0e38f, den = 0.f;
    float4 acc = make_float4(0.f, 0.f, 0.f, 0.f);

    float4 kvb0, vvb0, kvb1, vvb1;
    float eb0 = 0.f, eb1 = 0.f;
    if (r0 < r1) {
        const int s = g_esrc[r0];
        kvb0 = ((const float4*)g_kd)[(size_t)s * 32 + lane];
        vvb0 = ((const float4*)g_vd)[(size_t)s * 32 + lane];
        eb0 = __ldg(&g_ebp[(size_t)r0 * HH + h]);
    }
    if (r0 + 1 < r1) {
        const int s = g_esrc[r0 + 1];
        kvb1 = ((const float4*)g_kd)[(size_t)s * 32 + lane];
        vvb1 = ((const float4*)g_vd)[(size_t)s * 32 + lane];
        eb1 = __ldg(&g_ebp[(size_t)(r0 + 1) * HH + h]);
    }

#define ATTN_BODY(KV, VV, EBV)                                              \
    {                                                                       \
        float p = qv.x * (KV).x + qv.y * (KV).y + qv.z * (KV).z + qv.w * (KV).w; \
        p += __shfl_xor_sync(0xffffffffu, p, 1);                            \
        p += __shfl_xor_sync(0xffffffffu, p, 2);                            \
        const float sc = p * 0.25f + (EBV);                                 \
        const float nm = fmaxf(m, sc);                                      \
        const float corr = __expf(m - nm);                                  \
        const float w = __expf(sc - nm);                                    \
        m = nm;                                                             \
        den = den * corr + w;                                               \
        acc.x = acc.x * corr + w * (VV).x;                                  \
        acc.y = acc.y * corr + w * (VV).y;                                  \
        acc.z = acc.z * corr + w * (VV).z;                                  \
        acc.w = acc.w * corr + w * (VV).w;                                  \
    }

    int i = r0;
    while (i < r1) {
        {
            float4 kv = kvb0, vv = vvb0; float ebv = eb0;
            if (i + 2 < r1) {
                const int ns = g_esrc[i + 2];
                kvb0 = ((const float4*)g_kd)[(size_t)ns * 32 + lane];
                vvb0 = ((const float4*)g_vd)[(size_t)ns * 32 + lane];
                eb0 = __ldg(&g_ebp[(size_t)(i + 2) * HH + h]);
            }
            ATTN_BODY(kv, vv, ebv);
        }
        i++;
        if (i >= r1) break;
        {
            float4 kv = kvb1, vv = vvb1; float ebv = eb1;
            if (i + 2 < r1) {
                const int ns = g_esrc[i + 2];
                kvb1 = ((const float4*)g_kd)[(size_t)ns * 32 + lane];
                vvb1 = ((const float4*)g_vd)[(size_t)ns * 32 + lane];
                eb1 = __ldg(&g_ebp[(size_t)(i + 2) * HH + h]);
            }
            ATTN_BODY(kv, vv, ebv);
        }
        i++;
    }
#undef ATTN_BODY

    const float inv = (den > 0.f) ? (1.f / den) : 0.f;
    acc.x *= inv; acc.y *= inv; acc.z *= inv; acc.w *= inv;
    ((float4*)g_agg)[(size_t)n * 32 + lane] = acc;
}

// ---------------- WMMA bf16-split GEMM core (R11 structure, 2 CTAs/SM) ----------------
#define LDS_AB 72
#define LDS_C 132

template <int BM>
struct TCLayout {
    static constexpr int A_BYTES = BM * LDS_AB * 2;
    static constexpr int B_BYTES = 128 * LDS_AB * 2;
    static constexpr int OFF_AH = 0;
    static constexpr int OFF_AL = A_BYTES;
    static constexpr int OFF_BH = 2 * A_BYTES;
    static constexpr int OFF_BL = 2 * A_BYTES + B_BYTES;
    static constexpr int SMEM = 2 * A_BYTES + 2 * B_BYTES;
};
#define SMEM_TC128 (TCLayout<128>::SMEM)   // 73728
#define SMEM_TC64  (TCLayout<64>::SMEM)    // 55296

template <int BM>
__device__ __forceinline__ void cvt_storeA(char* smem, int row, int c4, float4 v) {
    __nv_bfloat162 h0 = __floats2bfloat162_rn(v.x, v.y);
    __nv_bfloat162 h1 = __floats2bfloat162_rn(v.z, v.w);
    float2 f0 = __bfloat1622float2(h0);
    float2 f1 = __bfloat1622float2(h1);
    __nv_bfloat162 l0 = __floats2bfloat162_rn(v.x - f0.x, v.y - f0.y);
    __nv_bfloat162 l1 = __floats2bfloat162_rn(v.z - f1.x, v.w - f1.y);
    uint2 ph, pl;
    ph.x = *(uint32_t*)&h0; ph.y = *(uint32_t*)&h1;
    pl.x = *(uint32_t*)&l0; pl.y = *(uint32_t*)&l1;
    *(uint2*)(smem + TCLayout<BM>::OFF_AH + ((size_t)row * LDS_AB + c4) * 2) = ph;
    *(uint2*)(smem + TCLayout<BM>::OFF_AL + ((size_t)row * LDS_AB + c4) * 2) = pl;
}

// BNIN: A-load applies BN1 (coef computed in-kernel from bnSums/bnG/bnBeta).
// RESBN: residual gets BN1 likewise. STATS: epilogue emits column sum/sumsq.
template <int BM, bool RELU, bool BIAS, bool RES, bool BNIN, bool RESBN, bool STATS>
__device__ __forceinline__ void gemm_core(
    const float* __restrict__ X,
    const __nv_bfloat16* __restrict__ WH, const __nv_bfloat16* __restrict__ WL,
    const float* __restrict__ bias, const float* __restrict__ res,
    const float* __restrict__ bnSums, const float* __restrict__ bnG,
    const float* __restrict__ bnBeta,
    float* __restrict__ stats, float* __restrict__ Y,
    int M, int K, int Co, int bm, int bn, char* smem) {
    constexpr int RF = BM / 64;
    const int tid = threadIdx.x;
    const int warp = tid >> 5;
    const int wm = (warp & 3) * (BM / 4);
    const int wn = (warp >> 2) * 64;
    const uint32_t sb = (uint32_t)__cvta_generic_to_shared(smem);

    // in-kernel BN coefficient computation (removes bn_coef launches)
    __shared__ float sCoef[256];
    if (BNIN || RESBN) {
        if (tid < 128) {
            const float inv = 1.f / (float)NN;
            const float mu = bnSums[tid] * inv;
            const float var = bnSums[128 + tid] * inv - mu * mu;
            const float rs = rsqrtf(var + EPS);
            const float sc = rs * bnG[tid];
            sCoef[tid] = sc;
            sCoef[128 + tid] = bnBeta[tid] - mu * sc;
        }
        __syncthreads();
    }

    wmma::fragment<wmma::accumulator, 16, 16, 16, float> acc[RF][4];
#pragma unroll
    for (int i = 0; i < RF; i++)
#pragma unroll
        for (int j = 0; j < 4; j++)
            wmma::fill_fragment(acc[i][j], 0.f);

    const __nv_bfloat16* sAh = (const __nv_bfloat16*)(smem + TCLayout<BM>::OFF_AH);
    const __nv_bfloat16* sAl = (const __nv_bfloat16*)(smem + TCLayout<BM>::OFF_AL);
    const __nv_bfloat16* sBh = (const __nv_bfloat16*)(smem + TCLayout<BM>::OFF_BH);
    const __nv_bfloat16* sBl = (const __nv_bfloat16*)(smem + TCLayout<BM>::OFF_BL);

    const int nch = K >> 6;
    for (int ch = 0; ch < nch; ch++) {
        const int kc0 = ch << 6;
        __syncthreads();
        // B: async copy of preconverted bf16 hi/lo (overlaps with A conversion)
#pragma unroll
        for (int it = 0; it < 4; it++) {
            const int idx = tid + it * 256;
            const int row = idx >> 3;
            const int c8 = (idx & 7) << 3;
            const size_t g = (size_t)(bn + row) * K + kc0 + c8;
            const uint32_t so = sb + TCLayout<BM>::OFF_BH + (uint32_t)(row * LDS_AB + c8) * 2;
            cp_async16(so, WH + g);
            cp_async16(so + (TCLayout<BM>::OFF_BL - TCLayout<BM>::OFF_BH), WL + g);
        }
        CP_COMMIT();
        // A: convert BMx64 fp32 -> bf16 hi/lo
#pragma unroll
        for (int it = 0; it < BM / 16; it++) {
            const int idx = tid + it * 256;
            const int row = idx >> 4;
            const int c4 = (idx & 15) << 2;
            const int r = min(bm + row, M - 1);
            float4 v = *(const float4*)(X + (size_t)r * K + kc0 + c4);
            if (BNIN) {
                const int c = kc0 + c4;
                float4 s4 = *(const float4*)(sCoef + c);
                float4 t4 = *(const float4*)(sCoef + 128 + c);
                v.x = v.x * s4.x + t4.x; v.y = v.y * s4.y + t4.y;
                v.z = v.z * s4.z + t4.z; v.w = v.w * s4.w + t4.w;
            }
            cvt_storeA<BM>(smem, row, c4, v);
        }
        CP_WAIT0();
        __syncthreads();

#pragma unroll
        for (int ks = 0; ks < 4; ks++) {
            const int k0 = ks * 16;
            wmma::fragment<wmma::matrix_a, 16, 16, 16, __nv_bfloat16, wmma::row_major> ah[RF], al[RF];
#pragma unroll
            for (int i = 0; i < RF; i++) {
                wmma::load_matrix_sync(ah[i], sAh + (size_t)(wm + 16 * i) * LDS_AB + k0, LDS_AB);
                wmma::load_matrix_sync(al[i], sAl + (size_t)(wm + 16 * i) * LDS_AB + k0, LDS_AB);
            }
#pragma unroll
            for (int j = 0; j < 4; j++) {
                wmma::fragment<wmma::matrix_b, 16, 16, 16, __nv_bfloat16, wmma::col_major> bh, bl;
                wmma::load_matrix_sync(bh, sBh + (size_t)(wn + 16 * j) * LDS_AB + k0, LDS_AB);
                wmma::load_matrix_sync(bl, sBl + (size_t)(wn + 16 * j) * LDS_AB + k0, LDS_AB);
#pragma unroll
                for (int i = 0; i < RF; i++) {
                    wmma::mma_sync(acc[i][j], ah[i], bh, acc[i][j]);
                    wmma::mma_sync(acc[i][j], ah[i], bl, acc[i][j]);
                    wmma::mma_sync(acc[i][j], al[i], bh, acc[i][j]);
                }
            }
        }
    }

    // epilogue
    __syncthreads();
    float* sC = (float*)smem;
#pragma unroll
    for (int i = 0; i < RF; i++)
#pragma unroll
        for (int j = 0; j < 4; j++)
            wmma::store_matrix_sync(sC + (size_t)(wm + 16 * i) * LDS_C + wn + 16 * j,
                                    acc[i][j], LDS_C, wmma::mem_row_major);
    __syncthreads();

    float st_s[4] = {0.f, 0.f, 0.f, 0.f};
    float st_q[4] = {0.f, 0.f, 0.f, 0.f};
#pragma unroll
    for (int it = 0; it < BM / 8; it++) {
        const int idx = tid + it * 256;
        const int row = idx >> 5;
        const int c = (idx & 31) << 2;
        const int m = bm + row;
        if (m < M) {
            const int n = bn + c;
            float4 o = *(const float4*)(sC + (size_t)row * LDS_C + c);
            if (BIAS) {
                float4 b4 = *(const float4*)&bias[n];
                o.x += b4.x; o.y += b4.y; o.z += b4.z; o.w += b4.w;
            }
            if (RELU) {
                o.x = fmaxf(o.x, 0.f); o.y = fmaxf(o.y, 0.f);
                o.z = fmaxf(o.z, 0.f); o.w = fmaxf(o.w, 0.f);
            }
            if (RES) {
                float4 r4 = *(const float4*)&res[(size_t)m * Co + n];
                if (RESBN) {
                    float4 s4 = *(const float4*)(sCoef + c);
                    float4 t4 = *(const float4*)(sCoef + 128 + c);
                    r4.x = r4.x * s4.x + t4.x; r4.y = r4.y * s4.y + t4.y;
                    r4.z = r4.z * s4.z + t4.z; r4.w = r4.w * s4.w + t4.w;
                }
                o.x += r4.x; o.y += r4.y; o.z += r4.z; o.w += r4.w;
            }
            *(float4*)&Y[(size_t)m * Co + n] = o;
            if (STATS) {
                st_s[0] += o.x; st_s[1] += o.y; st_s[2] += o.z; st_s[3] += o.w;
                st_q[0] += o.x * o.x; st_q[1] += o.y * o.y;
                st_q[2] += o.z * o.z; st_q[3] += o.w * o.w;
            }
        }
    }
    if (STATS) {
        __syncthreads();
        float* sP = (float*)smem;
#pragma unroll
        for (int j = 0; j < 4; j++) { sP[tid * 8 + j] = st_s[j]; sP[tid * 8 + 4 + j] = st_q[j]; }
        __syncthreads();
        if (tid < 128) {
            const int cg = tid >> 2, sub = tid & 3;
            float s = 0.f, qq = 0.f;
#pragma unroll
            for (int rg = 0; rg < 8; rg++) {
                const int tt = rg * 32 + cg;
                s += sP[tt * 8 + sub];
                qq += sP[tt * 8 + 4 + sub];
            }
            atomicAdd(&stats[bn + tid], s);
            atomicAdd(&stats[128 + bn + tid], qq);
        }
    }
}

template <bool RELU, bool BIAS, bool RES, bool BNIN, bool RESBN, bool STATS>
__global__ void __launch_bounds__(256, 2)
tc_gemm_kernel(const float* __restrict__ X,
               const __nv_bfloat16* __restrict__ WH, const __nv_bfloat16* __restrict__ WL,
               const float* __restrict__ bias, const float* __restrict__ res,
               const float* __restrict__ bnSums, const float* __restrict__ bnG,
               const float* __restrict__ bnBeta,
               float* __restrict__ stats, float* __restrict__ Y, int M, int K, int Co) {
    extern __shared__ char smem[];
    gemm_core<128, RELU, BIAS, RES, BNIN, RESBN, STATS>(
        X, WH, WL, bias, res, bnSums, bnG, bnBeta, stats, Y, M, K, Co,
        blockIdx.x * 128, blockIdx.y * 128, smem);
}

template <bool RELU, bool BIAS, bool RES, bool BNIN, bool RESBN, bool STATS>
__global__ void __launch_bounds__(256, 3)
tc_gemm64_kernel(const float* __restrict__ X,
                 const __nv_bfloat16* __restrict__ WH, const __nv_bfloat16* __restrict__ WL,
                 const float* __restrict__ bias, const float* __restrict__ res,
                 const float* __restrict__ bnSums, const float* __restrict__ bnG,
                 const float* __restrict__ bnBeta,
                 float* __restrict__ stats, float* __restrict__ Y, int M, int K, int Co) {
    extern __shared__ char smem[];
    gemm_core<64, RELU, BIAS, RES, BNIN, RESBN, STATS>(
        X, WH, WL, bias, res, bnSums, bnG, bnBeta, stats, Y, M, K, Co,
        blockIdx.x * 64, blockIdx.y * 128, smem);
}

__global__ void __launch_bounds__(256, 2)
qkv_gemm_kernel(const float* __restrict__ q, const float* __restrict__ k,
                const float* __restrict__ v) {
    extern __shared__ char smem[];
    const int z = blockIdx.z;
    const float* X = (z == 0) ? q : (z == 1) ? k : v;
    float* Y = (z == 0) ? g_qd : (z == 1) ? g_kd : g_vd;
    gemm_core<128, false, false, false, false, false, false>(
        X, g_wh + z * 16384, g_wl + z * 16384,
        nullptr, nullptr, nullptr, nullptr, nullptr, nullptr, Y, NN, CD, CD,
        blockIdx.x * 128, 0, smem);
}

// ---------------- edge bias + dst histogram (fused) ----------------
__global__ void __launch_bounds__(256)
eb_kernel(const float* __restrict__ ef, const float* __restrict__ We,
          const float* __restrict__ be, const int* __restrict__ dst) {
    __shared__ float sWe[HH * EDD];
    __shared__ float sbe[HH];
    for (int i = threadIdx.x; i < HH * EDD; i += 256) sWe[i] = We[i];
    if (threadIdx.x < HH) sbe[threadIdx.x] = be[threadIdx.x];
    __syncthreads();

    const int e = blockIdx.x * 256 + threadIdx.x;
    atomicAdd(&g_cnt[dst[e]], 1);
    const float4* efp = (const float4*)(ef + (size_t)e * EDD);
    float acc[HH];
#pragma unroll
    for (int h = 0; h < HH; h++) acc[h] = sbe[h];
#pragma unroll
    for (int j4 = 0; j4 < EDD / 4; j4++) {
        float4 v = efp[j4];
#pragma unroll
        for (int h = 0; h < HH; h++) {
            float4 w = *(const float4*)&sWe[h * EDD + j4 * 4];
            acc[h] += v.x * w.x + v.y * w.y + v.z * w.z + v.w * w.w;
        }
    }
    float4 o0 = make_float4(acc[0], acc[1], acc[2], acc[3]);
    float4 o1 = make_float4(acc[4], acc[5], acc[6], acc[7]);
    ((float4*)g_eb)[(size_t)e * 2 + 0] = o0;
    ((float4*)g_eb)[(size_t)e * 2 + 1] = o1;
}

// ---------------- final apply: BN2 computed in-block from stats ----------------
__global__ void __launch_bounds__(256)
bn_apply_kernel(const float* __restrict__ X, float* __restrict__ Y,
                const float* __restrict__ sums,
                const float* __restrict__ g, const float* __restrict__ b) {
    __shared__ float sCoef[256];
    if (threadIdx.x < 128) {
        const int c = threadIdx.x;
        const float inv = 1.f / (float)NN;
        const float mu = sums[c] * inv;
        const float var = sums[128 + c] * inv - mu * mu;
        const float rs = rsqrtf(var + EPS);
        const float sc = rs * g[c];
        sCoef[c] = sc;
        sCoef[128 + c] = b[c] - mu * sc;
    }
    __syncthreads();
    const int i = blockIdx.x * 256 + threadIdx.x;
    const int c = i & (CD - 1);
    Y[i] = X[i] * sCoef[c] + sCoef[128 + c];
}

// ---------------- launcher ----------------
extern "C" void kernel_launch(void* const* d_in, const int* in_sizes, int n_in,
                              void* d_out, int out_size) {
    const float* q   = (const float*)d_in[0];
    const float* k   = (const float*)d_in[1];
    const float* v   = (const float*)d_in[2];
    const float* ef  = (const float*)d_in[3];
    const int*   src = (const int*)d_in[4];
    const int*   dst = (const int*)d_in[5];
    const float* Wq  = (const float*)d_in[6];
    const float* Wk  = (const float*)d_in[7];
    const float* Wv  = (const float*)d_in[8];
    const float* We  = (const float*)d_in[9];
    const float* be  = (const float*)d_in[10];
    const float* Wo  = (const float*)d_in[11];
    const float* W1  = (const float*)d_in[12];
    const float* b1  = (const float*)d_in[13];
    const float* W2  = (const float*)d_in[14];
    const float* b2  = (const float*)d_in[15];
    const float* g1  = (const float*)d_in[16];
    const float* bt1 = (const float*)d_in[17];
    const float* g2  = (const float*)d_in[18];
    const float* bt2 = (const float*)d_in[19];
    float* out = (float*)d_out;

    float* p_agg; cudaGetSymbolAddress((void**)&p_agg, g_agg);
    float* p_rst; cudaGetSymbolAddress((void**)&p_rst, g_rst);
    float* p_h1; cudaGetSymbolAddress((void**)&p_h1, g_h1);
    float* p_h2; cudaGetSymbolAddress((void**)&p_h2, g_h2);
    float* p_stats; cudaGetSymbolAddress((void**)&p_stats, g_stats);
    __nv_bfloat16* p_wh; cudaGetSymbolAddress((void**)&p_wh, g_wh);
    __nv_bfloat16* p_wl; cudaGetSymbolAddress((void**)&p_wl, g_wl);

    static cudaStream_t s2 = nullptr;
    static cudaEvent_t evF = nullptr, evJ = nullptr;
    if (!s2) {
        cudaStreamCreateWithFlags(&s2, cudaStreamNonBlocking);
        cudaEventCreateWithFlags(&evF, cudaEventDisableTiming);
        cudaEventCreateWithFlags(&evJ, cudaEventDisableTiming);
    }

    cudaFuncSetAttribute(qkv_gemm_kernel, cudaFuncAttributeMaxDynamicSharedMemorySize, SMEM_TC128);
    cudaFuncSetAttribute(tc_gemm64_kernel<false, false, true,  false, false, true >, cudaFuncAttributeMaxDynamicSharedMemorySize, SMEM_TC64);
    cudaFuncSetAttribute(tc_gemm_kernel<true,  true,  false, true,  false, false>, cudaFuncAttributeMaxDynamicSharedMemorySize, SMEM_TC128);
    cudaFuncSetAttribute(tc_gemm64_kernel<false, true,  true,  false, true,  true >, cudaFuncAttributeMaxDynamicSharedMemorySize, SMEM_TC64);

    // fork at t0: edge preprocessing on s2 runs concurrently with initconv+qkv
    cudaEventRecord(evF, 0);
    cudaStreamWaitEvent(s2, evF, 0);

    zerocnt_kernel<<<NB, 256, 0, s2>>>();
    eb_kernel<<<EE / 256, 256, 0, s2>>>(ef, We, be, dst);
    scan1_kernel<<<NB, 256, 0, s2>>>();
    scan2_kernel<<<1, 256, 0, s2>>>();
    scan3_kernel<<<NB, 256, 0, s2>>>();
    scatter_kernel<<<EE / 256, 256, 0, s2>>>(src, dst);
    cudaEventRecord(evJ, s2);

    initconv_kernel<<<WTOT / 256, 256>>>(Wq, Wk, Wv, Wo, W1, W2);

    const dim3 gQKV(313, 1, 3);
    const dim3 g64(625, 1);
    const dim3 gH(313, 2);

    qkv_gemm_kernel<<<gQKV, 256, SMEM_TC128>>>(q, k, v);

    cudaStreamWaitEvent(0, evJ, 0);
    attn_kernel<<<NN / 8, 256>>>();

    // out proj + residual, stats for BN1 fused (BM=64: 625 CTAs, no tail rows)
    tc_gemm64_kernel<false, false, true, false, false, true><<<g64, 256, SMEM_TC64>>>(
        p_agg, p_wh + WOFF_O, p_wl + WOFF_O, nullptr, q, nullptr, nullptr, nullptr,
        p_stats, p_rst, NN, CD, CD);

    // FFN: W1 computes BN1 coef in-kernel and applies on A-load
    tc_gemm_kernel<true, true, false, true, false, false><<<gH, 256, SMEM_TC128>>>(
        p_rst, p_wh + WOFF_1, p_wl + WOFF_1, b1, nullptr, p_stats, g1, bt1,
        nullptr, p_h1, NN, CD, C2);
    // W2 computes BN1 coef in-kernel, applies to residual, emits stats2
    tc_gemm64_kernel<false, true, true, false, true, true><<<g64, 256, SMEM_TC64>>>(
        p_h1, p_wh + WOFF_2, p_wl + WOFF_2, b2, p_rst, p_stats, g1, bt1,
        p_stats + 2 * CD, p_h2, NN, C2, CD);
    // final BN2 apply (coef computed in-block)
    bn_apply_kernel<<<NN * CD / 256, 256>>>(p_h2, out, p_stats + 2 * CD, g2, bt2);
}